// round 16
// baseline (speedup 1.0000x reference)
#include <cuda_runtime.h>
#include <cuda_fp16.h>
#include <mma.h>
#include <cstdint>

using namespace nvcuda;

#define NMAX 50000
#define EMAX 800000
#define H 64
#define PREP_BLOCKS 592   // 4 blocks/SM x 148 SMs, co-residency guaranteed

// Scratch (static device arrays; no dynamic allocation allowed)
__device__ __half        g_h[NMAX * H];    // fp16 messages g = (X@W)*dinv_src
__device__ __half        g_a[NMAX * H];    // fp16 aggregated sums (layer boundary)
__device__ int           g_cnt[NMAX];      // incoming-edge count (excl self loop)
__device__ float         g_dinv[NMAX];
__device__ float         g_w[NMAX];        // pooling weight: dinv_n + sum dinv[dst]
__device__ int           g_off[NMAX];      // CSR offsets
__device__ unsigned int  g_pack[EMAX];     // dst | (rank << 16)
__device__ int           g_csr[EMAX];      // CSR-sorted source ids per dst

// Control block (zeroed by prep block 0 in phase 1, barrier before use)
struct Ctl {
    int   done;
    int   state[64];     // 0=invalid 1=aggregate 2=prefix
    float q[H];          // weighted pooled vector (pre-W3)
};
__device__ Ctl g_ctl;
__device__ int g_aggval[64];    // guarded by state; no zeroing needed
__device__ int g_prefval[64];

// Self-resetting software grid barrier (all PREP_BLOCKS resident).
__device__ int          g_bar_count = 0;
__device__ volatile int g_bar_gen = 0;

__device__ __forceinline__ void grid_barrier() {
    __threadfence();
    __syncthreads();
    if (threadIdx.x == 0) {
        int gen = g_bar_gen;
        if (atomicAdd(&g_bar_count, 1) == PREP_BLOCKS - 1) {
            g_bar_count = 0;
            __threadfence();
            g_bar_gen = gen + 1;
        } else {
            while (g_bar_gen == gen) { }
        }
    }
    __syncthreads();
    __threadfence();
}

// ---------------------------------------------------------------------------
// Per-block int64/int32 detection (values < 50000 => odd 32-bit words all 0).
// ---------------------------------------------------------------------------
__device__ __forceinline__ int detect_is64(const int* ei, int* s_flag) {
    if (threadIdx.x < 32) {
        const unsigned int* w = (const unsigned int*)ei;
        unsigned int v = w[2 * threadIdx.x + 1] | w[2 * (threadIdx.x + 32) + 1];
        int all0 = __all_sync(0xffffffffu, v == 0u);
        if (threadIdx.x == 0) *s_flag = all0;
    }
    __syncthreads();
    return *s_flag;
}

// ---------------------------------------------------------------------------
// Persistent prep kernel: P1 hist+rank -> barrier -> P2 scan (+dinv,w init)
// -> barrier -> P3 fill + wsum (fused single edge pass).
// ---------------------------------------------------------------------------
__global__ void __launch_bounds__(256, 4) prep_kernel(const int* __restrict__ ei,
                                                      int E, int N) {
    __shared__ int s_flag;
    __shared__ int s_warp[8];
    __shared__ int s_exc;

    if (blockIdx.x == 0) {
        int* c = (int*)&g_ctl;
        int words = (int)(sizeof(Ctl) / 4);
        for (int i = threadIdx.x; i < words; i += 256) c[i] = 0;
    }
    bool is64 = detect_is64(ei, &s_flag);
    cudaGridDependencySynchronize();   // wait for g_cnt memset

    // ---- P1: histogram + pack(dst, rank), grid-stride, 4 edges/iter ----
    int tid_g = blockIdx.x * 256 + threadIdx.x;
    int stride4 = PREP_BLOCKS * 256 * 4;
    for (int base = tid_g * 4; base < E; base += stride4) {
        if (base + 3 < E) {
            int d0, d1, d2, d3;
            if (is64) {
                const int2* p = (const int2*)(ei) + E + base;
                int2 a = p[0], b = p[1], c = p[2], d = p[3];
                d0 = a.x; d1 = b.x; d2 = c.x; d3 = d.x;
            } else {
                d0 = ei[E + base + 0]; d1 = ei[E + base + 1];
                d2 = ei[E + base + 2]; d3 = ei[E + base + 3];
            }
            unsigned int r0 = atomicAdd(&g_cnt[d0], 1);
            unsigned int r1 = atomicAdd(&g_cnt[d1], 1);
            unsigned int r2 = atomicAdd(&g_cnt[d2], 1);
            unsigned int r3 = atomicAdd(&g_cnt[d3], 1);
            g_pack[base + 0] = (unsigned int)d0 | (r0 << 16);
            g_pack[base + 1] = (unsigned int)d1 | (r1 << 16);
            g_pack[base + 2] = (unsigned int)d2 | (r2 << 16);
            g_pack[base + 3] = (unsigned int)d3 | (r3 << 16);
        } else {
            for (int j = 0; j < 4; j++) {
                int e = base + j;
                if (e < E) {
                    int d = is64 ? ei[2 * E + 2 * e] : ei[E + e];
                    unsigned int r = atomicAdd(&g_cnt[d], 1);
                    g_pack[e] = (unsigned int)d | (r << 16);
                }
            }
        }
    }

    grid_barrier();

    // ---- P2: exclusive scan (decoupled lookback, blocks 0..SB-1) ----
    int SB = (N + 1023) / 1024;
    if ((int)blockIdx.x < SB) {
        int t = threadIdx.x;
        int bid = blockIdx.x;
        int base = bid * 1024 + t * 4;
        int v[4], tsum = 0;
#pragma unroll
        for (int j = 0; j < 4; j++) {
            int idx = base + j;
            v[j] = (idx < N) ? g_cnt[idx] : 0;
            tsum += v[j];
        }
        int lane = t & 31, w = t >> 5;
        int x = tsum;
#pragma unroll
        for (int o = 1; o < 32; o <<= 1) {
            int y = __shfl_up_sync(0xffffffffu, x, o);
            if (lane >= o) x += y;
        }
        if (lane == 31) s_warp[w] = x;
        __syncthreads();

        if (t == 0) {
            int total = 0;
#pragma unroll
            for (int i = 0; i < 8; i++) { int tmp = s_warp[i]; s_warp[i] = total; total += tmp; }
            int exc = 0;
            volatile int* state = g_ctl.state;
            if (bid == 0) {
                g_prefval[0] = total;
                __threadfence();
                state[0] = 2;
            } else {
                g_aggval[bid] = total;
                __threadfence();
                state[bid] = 1;
                int i = bid - 1;
                while (true) {
                    int st;
                    while ((st = state[i]) == 0) { }
                    if (st == 2) { exc += g_prefval[i]; break; }
                    exc += g_aggval[i];
                    i--;
                }
                g_prefval[bid] = exc + total;
                __threadfence();
                state[bid] = 2;
            }
            s_exc = exc;
        }
        __syncthreads();

        int run = x - tsum + s_warp[w] + s_exc;
#pragma unroll
        for (int j = 0; j < 4; j++) {
            int idx = base + j;
            if (idx < N) {
                float di = rsqrtf((float)(v[j] + 1));   // +1 self loop
                g_off[idx]  = run;
                g_dinv[idx] = di;
                g_w[idx]    = di;                        // self pooling term
                run += v[j];
            }
        }
    }

    grid_barrier();

    // ---- P3: fill CSR + wsum (fused edge pass) ----
    for (int base = tid_g * 4; base < E; base += stride4) {
        if (base + 3 < E) {
            int s0, s1, s2, s3;
            if (is64) {
                const int2* p = (const int2*)ei + base;
                int2 a = p[0], b = p[1], c = p[2], d = p[3];
                s0 = a.x; s1 = b.x; s2 = c.x; s3 = d.x;
            } else {
                s0 = ei[base + 0]; s1 = ei[base + 1];
                s2 = ei[base + 2]; s3 = ei[base + 3];
            }
            unsigned int p0 = g_pack[base + 0];
            unsigned int p1 = g_pack[base + 1];
            unsigned int p2 = g_pack[base + 2];
            unsigned int p3 = g_pack[base + 3];
            int d0 = (int)(p0 & 0xffffu), d1 = (int)(p1 & 0xffffu);
            int d2 = (int)(p2 & 0xffffu), d3 = (int)(p3 & 0xffffu);
            int o0 = g_off[d0], o1 = g_off[d1], o2 = g_off[d2], o3 = g_off[d3];
            g_csr[o0 + (int)(p0 >> 16)] = s0;
            g_csr[o1 + (int)(p1 >> 16)] = s1;
            g_csr[o2 + (int)(p2 >> 16)] = s2;
            g_csr[o3 + (int)(p3 >> 16)] = s3;
            atomicAdd(&g_w[s0], __ldg(&g_dinv[d0]));
            atomicAdd(&g_w[s1], __ldg(&g_dinv[d1]));
            atomicAdd(&g_w[s2], __ldg(&g_dinv[d2]));
            atomicAdd(&g_w[s3], __ldg(&g_dinv[d3]));
        } else {
            for (int j = 0; j < 4; j++) {
                int e = base + j;
                if (e < E) {
                    int s = is64 ? ei[2 * e] : ei[e];
                    unsigned int p = g_pack[e];
                    int d = (int)(p & 0xffffu);
                    g_csr[g_off[d] + (int)(p >> 16)] = s;
                    atomicAdd(&g_w[s], __ldg(&g_dinv[d]));
                }
            }
        }
    }
}

// ---------------------------------------------------------------------------
// Gather: 8 threads/node, each owns 8 features = one uint4 of fp16 per edge.
// ---------------------------------------------------------------------------
__device__ __forceinline__ void acc8(float* a, uint4 r) {
    const unsigned int rr[4] = {r.x, r.y, r.z, r.w};
#pragma unroll
    for (int q = 0; q < 4; q++) {
        float2 f = __half22float2(*reinterpret_cast<const __half2*>(&rr[q]));
        a[2 * q]     += f.x;
        a[2 * q + 1] += f.y;
    }
}

__device__ __forceinline__ void gather_node(float* a, int gn, int lane) {
    const uint4* gh = (const uint4*)g_h;   // 8 uint4 per node row
#pragma unroll
    for (int j = 0; j < 8; j++) a[j] = 0.f;
    acc8(a, __ldg(gh + (size_t)gn * 8 + lane));   // self message
    int e = g_off[gn];
    int end = e + g_cnt[gn];
    for (; e + 4 <= end; e += 4) {
        int s0 = __ldg(&g_csr[e]);
        int s1 = __ldg(&g_csr[e + 1]);
        int s2 = __ldg(&g_csr[e + 2]);
        int s3 = __ldg(&g_csr[e + 3]);
        uint4 r0 = __ldg(gh + (size_t)s0 * 8 + lane);
        uint4 r1 = __ldg(gh + (size_t)s1 * 8 + lane);
        uint4 r2 = __ldg(gh + (size_t)s2 * 8 + lane);
        uint4 r3 = __ldg(gh + (size_t)s3 * 8 + lane);
        acc8(a, r0);
        acc8(a, r1);
        acc8(a, r2);
        acc8(a, r3);
    }
    for (; e < end; e++) {
        int s = __ldg(&g_csr[e]);
        acc8(a, __ldg(gh + (size_t)s * 8 + lane));
    }
}

// Aggregate (layer 1->2 boundary): raw fp16 sums to g_a.
__global__ __launch_bounds__(256) void agg_kernel(int N) {
    cudaGridDependencySynchronize();   // g_h + CSR must be ready
    int idx = blockIdx.x * blockDim.x + threadIdx.x;
    int node = idx >> 3, lane = idx & 7;
    if (node >= N) return;
    float a[8];
    gather_node(a, node, lane);
    unsigned int wbuf[4];
#pragma unroll
    for (int q = 0; q < 4; q++) {
        __half2 h = __floats2half2_rn(a[2 * q], a[2 * q + 1]);
        wbuf[q] = *reinterpret_cast<unsigned int*>(&h);
    }
    *(uint4*)(g_a + (size_t)node * H + lane * 8) =
        make_uint4(wbuf[0], wbuf[1], wbuf[2], wbuf[3]);
}

// ---------------------------------------------------------------------------
// TERMINAL aggregate (layer 2->3): gather h2-messages, apply
// xs = relu(a*dinv + b2), accumulate q[f] += (w_n*dinv_n) * xs[f].
// The LAST block then computes colsum = q @ W3 in fp32 and emits
// out = sum_f (colsum_f/N + b3_f) * fcW_f + fcb.  No layer-3 GEMM kernel.
// ---------------------------------------------------------------------------
__global__ __launch_bounds__(256) void aggfinal_kernel(
    int N, const float* __restrict__ b2, const float* __restrict__ W3,
    const float* __restrict__ b3, const float* __restrict__ fcW,
    const float* __restrict__ fcb, float* __restrict__ out) {
    __shared__ float s_q[H];
    __shared__ int s_last;
    if (threadIdx.x < H) s_q[threadIdx.x] = 0.f;
    cudaGridDependencySynchronize();   // g_h from gemm2w must be ready
    __syncthreads();

    int idx = blockIdx.x * blockDim.x + threadIdx.x;
    int node = idx >> 3, lane = idx & 7;
    if (node < N) {
        float a[8];
        gather_node(a, node, lane);
        float di = g_dinv[node];
        float wn = g_w[node] * di;     // pooling weight w'_n
#pragma unroll
        for (int j = 0; j < 8; j++) {
            int f = lane * 8 + j;
            float xs = fmaxf(fmaf(a[j], di, __ldg(&b2[f])), 0.f);
            atomicAdd(&s_q[f], wn * xs);
        }
    }
    __syncthreads();
    if (threadIdx.x < H) atomicAdd(&g_ctl.q[threadIdx.x], s_q[threadIdx.x]);
    __threadfence();
    if (threadIdx.x == 0)
        s_last = (atomicAdd(&g_ctl.done, 1) == (int)gridDim.x - 1);
    __syncthreads();

    if (s_last) {
        // q @ W3 (fp32 GEMV) + mean + b3 + FC, all in one block.
        __shared__ float s_qv[H];
        __shared__ float s_p[2];
        if (threadIdx.x < H) s_qv[threadIdx.x] = g_ctl.q[threadIdx.x];
        __syncthreads();
        if (threadIdx.x < H) {
            int f = threadIdx.x;
            float col = 0.f;
#pragma unroll 8
            for (int k = 0; k < H; k++)
                col = fmaf(s_qv[k], __ldg(&W3[k * H + f]), col);
            float v = (col / (float)N + b3[f]) * fcW[f];
#pragma unroll
            for (int o = 16; o > 0; o >>= 1)
                v += __shfl_down_sync(0xffffffffu, v, o);
            if ((f & 31) == 0) s_p[f >> 5] = v;
        }
        __syncthreads();
        if (threadIdx.x == 0) out[0] = s_p[0] + s_p[1] + fcb[0];
    }
}

// ---------------------------------------------------------------------------
// Layer 1 GEMM: x[N,10] @ W1[10,64]. Grid sync just before the dinv epilogue,
// so the X/W load + GEMM overlap prep's drain under PDL.
// ---------------------------------------------------------------------------
__global__ __launch_bounds__(256) void gemm1_kernel(const float* __restrict__ X,
                                                    const float* __restrict__ W,
                                                    int N) {
    __shared__ float xs[644];        // 64 nodes x 10 feats, flat
    __shared__ float ws[10][64];
    int node0 = blockIdx.x * 64;
    int t = threadIdx.x;

    for (int i = t; i < 640; i += 256) ws[i >> 6][i & 63] = W[i];
    if (node0 + 64 <= N) {
        if (t < 160)
            *(float4*)&xs[t * 4] = __ldg((const float4*)(X + (size_t)node0 * 10) + t);
    } else {
        for (int i = t; i < 640; i += 256) {
            int n = i / 10, k = i - n * 10;
            xs[i] = (node0 + n < N) ? X[(size_t)(node0 + n) * 10 + k] : 0.f;
        }
    }
    __syncthreads();

    int tx = t & 15, ty = t >> 4;
    float acc[4][4];
#pragma unroll
    for (int i = 0; i < 4; i++)
#pragma unroll
        for (int j = 0; j < 4; j++) acc[i][j] = 0.f;

#pragma unroll
    for (int k = 0; k < 10; k++) {
        float4 wv = *(const float4*)&ws[k][tx * 4];
#pragma unroll
        for (int i = 0; i < 4; i++) {
            float xa = xs[(ty * 4 + i) * 10 + k];
            acc[i][0] = fmaf(xa, wv.x, acc[i][0]);
            acc[i][1] = fmaf(xa, wv.y, acc[i][1]);
            acc[i][2] = fmaf(xa, wv.z, acc[i][2]);
            acc[i][3] = fmaf(xa, wv.w, acc[i][3]);
        }
    }

    cudaGridDependencySynchronize();   // dinv from prep needed only now

#pragma unroll
    for (int i = 0; i < 4; i++) {
        int gn = node0 + ty * 4 + i;
        if (gn < N) {
            float di = g_dinv[gn];
            __half2* hp = (__half2*)(g_h + (size_t)gn * H + tx * 4);
            hp[0] = __floats2half2_rn(acc[i][0] * di, acc[i][1] * di);
            hp[1] = __floats2half2_rn(acc[i][2] * di, acc[i][3] * di);
        }
    }
}

// ---------------------------------------------------------------------------
// Layer 2 GEMM on TENSOR CORES with SPLIT-W (fp32-class W precision).
// Input  = relu(g_a * dinv + bias_prev) in fp16; output fp16 messages.
// ---------------------------------------------------------------------------
__global__ __launch_bounds__(256) void gemm2w_kernel(
    const float* __restrict__ W, const float* __restrict__ bias_prev, int N) {
    __shared__ __align__(16) __half xs[64][72];
    __shared__ __align__(16) __half whi[64][72];
    __shared__ __align__(16) __half wlo[64][72];
    __shared__ float os[64][68];
    __shared__ float bsh[64];

    int node0 = blockIdx.x * 64;
    int t = threadIdx.x;

    if (t < 64) bsh[t] = bias_prev[t];
    for (int i = t; i < 4096; i += 256) {
        float w = W[i];
        __half hi = __float2half(w);
        whi[i >> 6][i & 63] = hi;
        wlo[i >> 6][i & 63] = __float2half(w - __half2float(hi));
    }

    cudaGridDependencySynchronize();   // g_a from agg needed only now
    __syncthreads();

    for (int i = t; i < 512; i += 256) {
        int n = i >> 3, c = i & 7;
        int gn = node0 + n;
        if (gn < N) {
            uint4 r = __ldg((const uint4*)(g_a + (size_t)gn * H + c * 8));
            float di = g_dinv[gn];
            const unsigned int rr[4] = {r.x, r.y, r.z, r.w};
#pragma unroll
            for (int q = 0; q < 4; q++) {
                float2 f = __half22float2(*reinterpret_cast<const __half2*>(&rr[q]));
                xs[n][c * 8 + 2 * q] =
                    __float2half(fmaxf(fmaf(f.x, di, bsh[c * 8 + 2 * q]), 0.f));
                xs[n][c * 8 + 2 * q + 1] =
                    __float2half(fmaxf(fmaf(f.y, di, bsh[c * 8 + 2 * q + 1]), 0.f));
            }
        } else {
#pragma unroll
            for (int q = 0; q < 8; q++) xs[n][c * 8 + q] = __half(0.f);
        }
    }
    __syncthreads();

    int wid = t >> 5;
#pragma unroll
    for (int rep = 0; rep < 2; rep++) {
        int tile = wid + rep * 8;
        int mi = tile >> 2, ni = tile & 3;
        wmma::fragment<wmma::accumulator, 16, 16, 16, float> c;
        wmma::fill_fragment(c, 0.f);
#pragma unroll
        for (int k0 = 0; k0 < 4; k0++) {
            wmma::fragment<wmma::matrix_a, 16, 16, 16, __half, wmma::row_major> a;
            wmma::fragment<wmma::matrix_b, 16, 16, 16, __half, wmma::row_major> bh;
            wmma::fragment<wmma::matrix_b, 16, 16, 16, __half, wmma::row_major> bl;
            wmma::load_matrix_sync(a, &xs[mi * 16][k0 * 16], 72);
            wmma::load_matrix_sync(bh, &whi[k0 * 16][ni * 16], 72);
            wmma::load_matrix_sync(bl, &wlo[k0 * 16][ni * 16], 72);
            wmma::mma_sync(c, a, bh, c);
            wmma::mma_sync(c, a, bl, c);
        }
        wmma::store_matrix_sync(&os[mi * 16][ni * 16], c, 68, wmma::mem_row_major);
    }
    __syncthreads();

    for (int i = t; i < 512; i += 256) {
        int n = i >> 3, c = i & 7;
        int gn = node0 + n;
        if (gn < N) {
            float di = g_dinv[gn];
            unsigned int wbuf[4];
#pragma unroll
            for (int q = 0; q < 4; q++) {
                __half2 h = __floats2half2_rn(os[n][c * 8 + 2 * q] * di,
                                              os[n][c * 8 + 2 * q + 1] * di);
                wbuf[q] = *reinterpret_cast<unsigned int*>(&h);
            }
            *(uint4*)(g_h + (size_t)gn * H + c * 8) =
                make_uint4(wbuf[0], wbuf[1], wbuf[2], wbuf[3]);
        }
    }
}

// ---------------------------------------------------------------------------
// Host: PDL launch helper
// ---------------------------------------------------------------------------
template <typename K, typename... Args>
static void launch_pdl(K kernel, dim3 grid, dim3 block, Args... args) {
    cudaLaunchConfig_t cfg = {};
    cfg.gridDim = grid;
    cfg.blockDim = block;
    cfg.dynamicSmemBytes = 0;
    cfg.stream = 0;
    cudaLaunchAttribute attr[1];
    attr[0].id = cudaLaunchAttributeProgrammaticStreamSerialization;
    attr[0].val.programmaticStreamSerializationAllowed = 1;
    cfg.attrs = attr;
    cfg.numAttrs = 1;
    cudaLaunchKernelEx(&cfg, kernel, args...);
}

extern "C" void kernel_launch(void* const* d_in, const int* in_sizes, int n_in,
                              void* d_out, int out_size) {
    const float* x   = (const float*)d_in[0];
    const void*  ei  = d_in[1];
    const float* W1  = (const float*)d_in[2];
    const float* b1  = (const float*)d_in[3];
    const float* W2  = (const float*)d_in[4];
    const float* b2  = (const float*)d_in[5];
    const float* W3  = (const float*)d_in[6];
    const float* b3  = (const float*)d_in[7];
    const float* fcW = (const float*)d_in[8];
    const float* fcb = (const float*)d_in[9];
    float* out = (float*)d_out;

    int FIN1 = in_sizes[2] / H;      // 10
    int N = in_sizes[0] / FIN1;      // 50000
    int E = in_sizes[1] / 2;         // 800000

    int gblocks = (N + 63) / 64;
    int ablocks = (N * 8 + 255) / 256;

    // Zero edge counters (Ctl is zeroed inside prep block 0, pre-barrier).
    void* cnt_ptr = nullptr;
    cudaGetSymbolAddress(&cnt_ptr, g_cnt);
    cudaMemsetAsync(cnt_ptr, 0, (size_t)N * sizeof(int));

    // Single-stream PDL chain; layer-3 GEMM folded into aggfinal (q @ W3).
    launch_pdl(prep_kernel, PREP_BLOCKS, 256, (const int*)ei, E, N);
    launch_pdl(gemm1_kernel, gblocks, 256, x, W1, N);
    launch_pdl(agg_kernel, ablocks, 256, N);
    launch_pdl(gemm2w_kernel, gblocks, 256, W2, b1, N);
    launch_pdl(aggfinal_kernel, ablocks, 256, N, b2, W3, b3, fcW, fcb, out);
}

// round 17
// speedup vs baseline: 1.0854x; 1.0854x over previous
#include <cuda_runtime.h>
#include <cuda_fp16.h>
#include <mma.h>
#include <cstdint>

using namespace nvcuda;

#define NMAX 50000
#define EMAX 800000
#define H 64
#define PREP_BLOCKS 592   // 4 blocks/SM x 148 SMs, co-residency guaranteed

// Scratch (static device arrays; no dynamic allocation allowed)
__device__ __half        g_h[NMAX * H];    // fp16 messages g = (X@W)*dinv_src
__device__ __half        g_a[NMAX * H];    // fp16 aggregated sums (layer boundary)
__device__ int           g_cnt[NMAX];      // incoming-edge count (excl self loop)
__device__ float         g_dinv[NMAX];
__device__ float         g_w[NMAX];        // pooling weight: dinv_n + sum dinv[dst]
__device__ int           g_off[NMAX];      // CSR offsets
__device__ unsigned int  g_pack[EMAX];     // dst | (rank << 16)
__device__ int           g_csr[EMAX];      // CSR-sorted source ids per dst

// Control block (zeroed by prep block 0 in phase 1, barrier before use)
struct Ctl {
    int   done;
    int   state[64];     // 0=invalid 1=aggregate 2=prefix
    float q[H];          // weighted pooled vector (pre-W3)
};
__device__ Ctl g_ctl;
__device__ int g_aggval[64];    // guarded by state; no zeroing needed
__device__ int g_prefval[64];

// Self-resetting software grid barrier (all PREP_BLOCKS resident).
__device__ int          g_bar_count = 0;
__device__ volatile int g_bar_gen = 0;

__device__ __forceinline__ void grid_barrier() {
    __threadfence();
    __syncthreads();
    if (threadIdx.x == 0) {
        int gen = g_bar_gen;
        if (atomicAdd(&g_bar_count, 1) == PREP_BLOCKS - 1) {
            g_bar_count = 0;
            __threadfence();
            g_bar_gen = gen + 1;
        } else {
            while (g_bar_gen == gen) { }
        }
    }
    __syncthreads();
    __threadfence();
}

// ---------------------------------------------------------------------------
// Per-block int64/int32 detection (values < 50000 => odd 32-bit words all 0).
// ---------------------------------------------------------------------------
__device__ __forceinline__ int detect_is64(const int* ei, int* s_flag) {
    if (threadIdx.x < 32) {
        const unsigned int* w = (const unsigned int*)ei;
        unsigned int v = w[2 * threadIdx.x + 1] | w[2 * (threadIdx.x + 32) + 1];
        int all0 = __all_sync(0xffffffffu, v == 0u);
        if (threadIdx.x == 0) *s_flag = all0;
    }
    __syncthreads();
    return *s_flag;
}

// ---------------------------------------------------------------------------
// Persistent prep kernel: P1 hist+rank -> barrier -> P2 scan (+dinv,w init)
// -> barrier -> P3 fill + wsum (fused single edge pass).
// ---------------------------------------------------------------------------
__global__ void __launch_bounds__(256, 4) prep_kernel(const int* __restrict__ ei,
                                                      int E, int N) {
    __shared__ int s_flag;
    __shared__ int s_warp[8];
    __shared__ int s_exc;

    if (blockIdx.x == 0) {
        int* c = (int*)&g_ctl;
        int words = (int)(sizeof(Ctl) / 4);
        for (int i = threadIdx.x; i < words; i += 256) c[i] = 0;
    }
    bool is64 = detect_is64(ei, &s_flag);
    cudaGridDependencySynchronize();   // wait for g_cnt memset

    // ---- P1: histogram + pack(dst, rank), grid-stride, 4 edges/iter ----
    int tid_g = blockIdx.x * 256 + threadIdx.x;
    int stride4 = PREP_BLOCKS * 256 * 4;
    for (int base = tid_g * 4; base < E; base += stride4) {
        if (base + 3 < E) {
            int d0, d1, d2, d3;
            if (is64) {
                const int2* p = (const int2*)(ei) + E + base;
                int2 a = p[0], b = p[1], c = p[2], d = p[3];
                d0 = a.x; d1 = b.x; d2 = c.x; d3 = d.x;
            } else {
                d0 = ei[E + base + 0]; d1 = ei[E + base + 1];
                d2 = ei[E + base + 2]; d3 = ei[E + base + 3];
            }
            unsigned int r0 = atomicAdd(&g_cnt[d0], 1);
            unsigned int r1 = atomicAdd(&g_cnt[d1], 1);
            unsigned int r2 = atomicAdd(&g_cnt[d2], 1);
            unsigned int r3 = atomicAdd(&g_cnt[d3], 1);
            g_pack[base + 0] = (unsigned int)d0 | (r0 << 16);
            g_pack[base + 1] = (unsigned int)d1 | (r1 << 16);
            g_pack[base + 2] = (unsigned int)d2 | (r2 << 16);
            g_pack[base + 3] = (unsigned int)d3 | (r3 << 16);
        } else {
            for (int j = 0; j < 4; j++) {
                int e = base + j;
                if (e < E) {
                    int d = is64 ? ei[2 * E + 2 * e] : ei[E + e];
                    unsigned int r = atomicAdd(&g_cnt[d], 1);
                    g_pack[e] = (unsigned int)d | (r << 16);
                }
            }
        }
    }

    grid_barrier();

    // ---- P2: exclusive scan (decoupled lookback, blocks 0..SB-1) ----
    int SB = (N + 1023) / 1024;
    if ((int)blockIdx.x < SB) {
        int t = threadIdx.x;
        int bid = blockIdx.x;
        int base = bid * 1024 + t * 4;
        int v[4], tsum = 0;
#pragma unroll
        for (int j = 0; j < 4; j++) {
            int idx = base + j;
            v[j] = (idx < N) ? g_cnt[idx] : 0;
            tsum += v[j];
        }
        int lane = t & 31, w = t >> 5;
        int x = tsum;
#pragma unroll
        for (int o = 1; o < 32; o <<= 1) {
            int y = __shfl_up_sync(0xffffffffu, x, o);
            if (lane >= o) x += y;
        }
        if (lane == 31) s_warp[w] = x;
        __syncthreads();

        if (t == 0) {
            int total = 0;
#pragma unroll
            for (int i = 0; i < 8; i++) { int tmp = s_warp[i]; s_warp[i] = total; total += tmp; }
            int exc = 0;
            volatile int* state = g_ctl.state;
            if (bid == 0) {
                g_prefval[0] = total;
                __threadfence();
                state[0] = 2;
            } else {
                g_aggval[bid] = total;
                __threadfence();
                state[bid] = 1;
                int i = bid - 1;
                while (true) {
                    int st;
                    while ((st = state[i]) == 0) { }
                    if (st == 2) { exc += g_prefval[i]; break; }
                    exc += g_aggval[i];
                    i--;
                }
                g_prefval[bid] = exc + total;
                __threadfence();
                state[bid] = 2;
            }
            s_exc = exc;
        }
        __syncthreads();

        int run = x - tsum + s_warp[w] + s_exc;
#pragma unroll
        for (int j = 0; j < 4; j++) {
            int idx = base + j;
            if (idx < N) {
                float di = rsqrtf((float)(v[j] + 1));   // +1 self loop
                g_off[idx]  = run;
                g_dinv[idx] = di;
                g_w[idx]    = di;                        // self pooling term
                run += v[j];
            }
        }
    }

    grid_barrier();

    // ---- P3: fill CSR + wsum (fused edge pass) ----
    for (int base = tid_g * 4; base < E; base += stride4) {
        if (base + 3 < E) {
            int s0, s1, s2, s3;
            if (is64) {
                const int2* p = (const int2*)ei + base;
                int2 a = p[0], b = p[1], c = p[2], d = p[3];
                s0 = a.x; s1 = b.x; s2 = c.x; s3 = d.x;
            } else {
                s0 = ei[base + 0]; s1 = ei[base + 1];
                s2 = ei[base + 2]; s3 = ei[base + 3];
            }
            unsigned int p0 = g_pack[base + 0];
            unsigned int p1 = g_pack[base + 1];
            unsigned int p2 = g_pack[base + 2];
            unsigned int p3 = g_pack[base + 3];
            int d0 = (int)(p0 & 0xffffu), d1 = (int)(p1 & 0xffffu);
            int d2 = (int)(p2 & 0xffffu), d3 = (int)(p3 & 0xffffu);
            int o0 = g_off[d0], o1 = g_off[d1], o2 = g_off[d2], o3 = g_off[d3];
            g_csr[o0 + (int)(p0 >> 16)] = s0;
            g_csr[o1 + (int)(p1 >> 16)] = s1;
            g_csr[o2 + (int)(p2 >> 16)] = s2;
            g_csr[o3 + (int)(p3 >> 16)] = s3;
            atomicAdd(&g_w[s0], __ldg(&g_dinv[d0]));
            atomicAdd(&g_w[s1], __ldg(&g_dinv[d1]));
            atomicAdd(&g_w[s2], __ldg(&g_dinv[d2]));
            atomicAdd(&g_w[s3], __ldg(&g_dinv[d3]));
        } else {
            for (int j = 0; j < 4; j++) {
                int e = base + j;
                if (e < E) {
                    int s = is64 ? ei[2 * e] : ei[e];
                    unsigned int p = g_pack[e];
                    int d = (int)(p & 0xffffu);
                    g_csr[g_off[d] + (int)(p >> 16)] = s;
                    atomicAdd(&g_w[s], __ldg(&g_dinv[d]));
                }
            }
        }
    }
}

// ---------------------------------------------------------------------------
// Gather: 8 threads/node, each owns 8 features = one uint4 of fp16 per edge.
// ---------------------------------------------------------------------------
__device__ __forceinline__ void acc8(float* a, uint4 r) {
    const unsigned int rr[4] = {r.x, r.y, r.z, r.w};
#pragma unroll
    for (int q = 0; q < 4; q++) {
        float2 f = __half22float2(*reinterpret_cast<const __half2*>(&rr[q]));
        a[2 * q]     += f.x;
        a[2 * q + 1] += f.y;
    }
}

__device__ __forceinline__ void gather_node(float* a, int gn, int lane) {
    const uint4* gh = (const uint4*)g_h;   // 8 uint4 per node row
#pragma unroll
    for (int j = 0; j < 8; j++) a[j] = 0.f;
    acc8(a, __ldg(gh + (size_t)gn * 8 + lane));   // self message
    int e = g_off[gn];
    int end = e + g_cnt[gn];
    for (; e + 4 <= end; e += 4) {
        int s0 = __ldg(&g_csr[e]);
        int s1 = __ldg(&g_csr[e + 1]);
        int s2 = __ldg(&g_csr[e + 2]);
        int s3 = __ldg(&g_csr[e + 3]);
        uint4 r0 = __ldg(gh + (size_t)s0 * 8 + lane);
        uint4 r1 = __ldg(gh + (size_t)s1 * 8 + lane);
        uint4 r2 = __ldg(gh + (size_t)s2 * 8 + lane);
        uint4 r3 = __ldg(gh + (size_t)s3 * 8 + lane);
        acc8(a, r0);
        acc8(a, r1);
        acc8(a, r2);
        acc8(a, r3);
    }
    for (; e < end; e++) {
        int s = __ldg(&g_csr[e]);
        acc8(a, __ldg(gh + (size_t)s * 8 + lane));
    }
}

// Aggregate (layer 1->2 boundary): raw fp16 sums to g_a.
__global__ __launch_bounds__(256) void agg_kernel(int N) {
    cudaGridDependencySynchronize();   // g_h + CSR must be ready
    int idx = blockIdx.x * blockDim.x + threadIdx.x;
    int node = idx >> 3, lane = idx & 7;
    if (node >= N) return;
    float a[8];
    gather_node(a, node, lane);
    unsigned int wbuf[4];
#pragma unroll
    for (int q = 0; q < 4; q++) {
        __half2 h = __floats2half2_rn(a[2 * q], a[2 * q + 1]);
        wbuf[q] = *reinterpret_cast<unsigned int*>(&h);
    }
    *(uint4*)(g_a + (size_t)node * H + lane * 8) =
        make_uint4(wbuf[0], wbuf[1], wbuf[2], wbuf[3]);
}

// ---------------------------------------------------------------------------
// TERMINAL aggregate (layer 2->3): gather h2-messages, apply
// xs = relu(a*dinv + b2), accumulate q[f] += (w_n*dinv_n)*xs[f] via
// shuffle + per-warp partials + block tree (NO conflicted smem atomics).
// The LAST block computes colsum = q @ W3 (fp32) and emits the FC output.
// ---------------------------------------------------------------------------
__global__ __launch_bounds__(256) void aggfinal_kernel(
    int N, const float* __restrict__ b2, const float* __restrict__ W3,
    const float* __restrict__ b3, const float* __restrict__ fcW,
    const float* __restrict__ fcb, float* __restrict__ out) {
    __shared__ float s_part[8][64];    // per-warp feature partials
    __shared__ int s_last;
    cudaGridDependencySynchronize();   // g_h from gemm2w must be ready

    int idx = blockIdx.x * blockDim.x + threadIdx.x;
    int node = idx >> 3, lane = idx & 7;
    float vals[8];
    if (node < N) {
        float a[8];
        gather_node(a, node, lane);
        float di = g_dinv[node];
        float wn = g_w[node] * di;     // pooling weight w'_n
#pragma unroll
        for (int j = 0; j < 8; j++)
            vals[j] = wn * fmaxf(fmaf(a[j], di, __ldg(&b2[lane * 8 + j])), 0.f);
    } else {
#pragma unroll
        for (int j = 0; j < 8; j++) vals[j] = 0.f;
    }

    // Reduce the 4 nodes of each warp: lanes {l, l+8, l+16, l+24} share a slot.
    int wlane = threadIdx.x & 31, wid = threadIdx.x >> 5;
#pragma unroll
    for (int j = 0; j < 8; j++) {
        float v = vals[j];
        v += __shfl_down_sync(0xffffffffu, v, 8);
        v += __shfl_down_sync(0xffffffffu, v, 16);
        if (wlane < 8) s_part[wid][wlane * 8 + j] = v;
    }
    __syncthreads();

    if (threadIdx.x < 64) {
        float q = 0.f;
#pragma unroll
        for (int w = 0; w < 8; w++) q += s_part[w][threadIdx.x];
        atomicAdd(&g_ctl.q[threadIdx.x], q);
    }
    __threadfence();
    if (threadIdx.x == 0)
        s_last = (atomicAdd(&g_ctl.done, 1) == (int)gridDim.x - 1);
    __syncthreads();

    if (s_last) {
        // q @ W3 (fp32 GEMV) + mean + b3 + FC, all in one block.
        __shared__ float s_qv[H];
        __shared__ float s_p[2];
        if (threadIdx.x < H) s_qv[threadIdx.x] = g_ctl.q[threadIdx.x];
        __syncthreads();
        if (threadIdx.x < H) {
            int f = threadIdx.x;
            float col = 0.f;
#pragma unroll 8
            for (int k = 0; k < H; k++)
                col = fmaf(s_qv[k], __ldg(&W3[k * H + f]), col);
            float v = (col / (float)N + b3[f]) * fcW[f];
#pragma unroll
            for (int o = 16; o > 0; o >>= 1)
                v += __shfl_down_sync(0xffffffffu, v, o);
            if ((f & 31) == 0) s_p[f >> 5] = v;
        }
        __syncthreads();
        if (threadIdx.x == 0) out[0] = s_p[0] + s_p[1] + fcb[0];
    }
}

// ---------------------------------------------------------------------------
// Layer 1 GEMM: x[N,10] @ W1[10,64]. Grid sync just before the dinv epilogue,
// so the X/W load + GEMM overlap prep's drain under PDL.
// ---------------------------------------------------------------------------
__global__ __launch_bounds__(256) void gemm1_kernel(const float* __restrict__ X,
                                                    const float* __restrict__ W,
                                                    int N) {
    __shared__ float xs[644];        // 64 nodes x 10 feats, flat
    __shared__ float ws[10][64];
    int node0 = blockIdx.x * 64;
    int t = threadIdx.x;

    for (int i = t; i < 640; i += 256) ws[i >> 6][i & 63] = W[i];
    if (node0 + 64 <= N) {
        if (t < 160)
            *(float4*)&xs[t * 4] = __ldg((const float4*)(X + (size_t)node0 * 10) + t);
    } else {
        for (int i = t; i < 640; i += 256) {
            int n = i / 10, k = i - n * 10;
            xs[i] = (node0 + n < N) ? X[(size_t)(node0 + n) * 10 + k] : 0.f;
        }
    }
    __syncthreads();

    int tx = t & 15, ty = t >> 4;
    float acc[4][4];
#pragma unroll
    for (int i = 0; i < 4; i++)
#pragma unroll
        for (int j = 0; j < 4; j++) acc[i][j] = 0.f;

#pragma unroll
    for (int k = 0; k < 10; k++) {
        float4 wv = *(const float4*)&ws[k][tx * 4];
#pragma unroll
        for (int i = 0; i < 4; i++) {
            float xa = xs[(ty * 4 + i) * 10 + k];
            acc[i][0] = fmaf(xa, wv.x, acc[i][0]);
            acc[i][1] = fmaf(xa, wv.y, acc[i][1]);
            acc[i][2] = fmaf(xa, wv.z, acc[i][2]);
            acc[i][3] = fmaf(xa, wv.w, acc[i][3]);
        }
    }

    cudaGridDependencySynchronize();   // dinv from prep needed only now

#pragma unroll
    for (int i = 0; i < 4; i++) {
        int gn = node0 + ty * 4 + i;
        if (gn < N) {
            float di = g_dinv[gn];
            __half2* hp = (__half2*)(g_h + (size_t)gn * H + tx * 4);
            hp[0] = __floats2half2_rn(acc[i][0] * di, acc[i][1] * di);
            hp[1] = __floats2half2_rn(acc[i][2] * di, acc[i][3] * di);
        }
    }
}

// ---------------------------------------------------------------------------
// Layer 2 GEMM on TENSOR CORES with SPLIT-W (fp32-class W precision).
// Input  = relu(g_a * dinv + bias_prev) in fp16; output fp16 messages.
// ---------------------------------------------------------------------------
__global__ __launch_bounds__(256) void gemm2w_kernel(
    const float* __restrict__ W, const float* __restrict__ bias_prev, int N) {
    __shared__ __align__(16) __half xs[64][72];
    __shared__ __align__(16) __half whi[64][72];
    __shared__ __align__(16) __half wlo[64][72];
    __shared__ float os[64][68];
    __shared__ float bsh[64];

    int node0 = blockIdx.x * 64;
    int t = threadIdx.x;

    if (t < 64) bsh[t] = bias_prev[t];
    for (int i = t; i < 4096; i += 256) {
        float w = W[i];
        __half hi = __float2half(w);
        whi[i >> 6][i & 63] = hi;
        wlo[i >> 6][i & 63] = __float2half(w - __half2float(hi));
    }

    cudaGridDependencySynchronize();   // g_a from agg needed only now
    __syncthreads();

    for (int i = t; i < 512; i += 256) {
        int n = i >> 3, c = i & 7;
        int gn = node0 + n;
        if (gn < N) {
            uint4 r = __ldg((const uint4*)(g_a + (size_t)gn * H + c * 8));
            float di = g_dinv[gn];
            const unsigned int rr[4] = {r.x, r.y, r.z, r.w};
#pragma unroll
            for (int q = 0; q < 4; q++) {
                float2 f = __half22float2(*reinterpret_cast<const __half2*>(&rr[q]));
                xs[n][c * 8 + 2 * q] =
                    __float2half(fmaxf(fmaf(f.x, di, bsh[c * 8 + 2 * q]), 0.f));
                xs[n][c * 8 + 2 * q + 1] =
                    __float2half(fmaxf(fmaf(f.y, di, bsh[c * 8 + 2 * q + 1]), 0.f));
            }
        } else {
#pragma unroll
            for (int q = 0; q < 8; q++) xs[n][c * 8 + q] = __half(0.f);
        }
    }
    __syncthreads();

    int wid = t >> 5;
#pragma unroll
    for (int rep = 0; rep < 2; rep++) {
        int tile = wid + rep * 8;
        int mi = tile >> 2, ni = tile & 3;
        wmma::fragment<wmma::accumulator, 16, 16, 16, float> c;
        wmma::fill_fragment(c, 0.f);
#pragma unroll
        for (int k0 = 0; k0 < 4; k0++) {
            wmma::fragment<wmma::matrix_a, 16, 16, 16, __half, wmma::row_major> a;
            wmma::fragment<wmma::matrix_b, 16, 16, 16, __half, wmma::row_major> bh;
            wmma::fragment<wmma::matrix_b, 16, 16, 16, __half, wmma::row_major> bl;
            wmma::load_matrix_sync(a, &xs[mi * 16][k0 * 16], 72);
            wmma::load_matrix_sync(bh, &whi[k0 * 16][ni * 16], 72);
            wmma::load_matrix_sync(bl, &wlo[k0 * 16][ni * 16], 72);
            wmma::mma_sync(c, a, bh, c);
            wmma::mma_sync(c, a, bl, c);
        }
        wmma::store_matrix_sync(&os[mi * 16][ni * 16], c, 68, wmma::mem_row_major);
    }
    __syncthreads();

    for (int i = t; i < 512; i += 256) {
        int n = i >> 3, c = i & 7;
        int gn = node0 + n;
        if (gn < N) {
            float di = g_dinv[gn];
            unsigned int wbuf[4];
#pragma unroll
            for (int q = 0; q < 4; q++) {
                __half2 h = __floats2half2_rn(os[n][c * 8 + 2 * q] * di,
                                              os[n][c * 8 + 2 * q + 1] * di);
                wbuf[q] = *reinterpret_cast<unsigned int*>(&h);
            }
            *(uint4*)(g_h + (size_t)gn * H + c * 8) =
                make_uint4(wbuf[0], wbuf[1], wbuf[2], wbuf[3]);
        }
    }
}

// ---------------------------------------------------------------------------
// Host: PDL launch helper
// ---------------------------------------------------------------------------
template <typename K, typename... Args>
static void launch_pdl(K kernel, dim3 grid, dim3 block, Args... args) {
    cudaLaunchConfig_t cfg = {};
    cfg.gridDim = grid;
    cfg.blockDim = block;
    cfg.dynamicSmemBytes = 0;
    cfg.stream = 0;
    cudaLaunchAttribute attr[1];
    attr[0].id = cudaLaunchAttributeProgrammaticStreamSerialization;
    attr[0].val.programmaticStreamSerializationAllowed = 1;
    cfg.attrs = attr;
    cfg.numAttrs = 1;
    cudaLaunchKernelEx(&cfg, kernel, args...);
}

extern "C" void kernel_launch(void* const* d_in, const int* in_sizes, int n_in,
                              void* d_out, int out_size) {
    const float* x   = (const float*)d_in[0];
    const void*  ei  = d_in[1];
    const float* W1  = (const float*)d_in[2];
    const float* b1  = (const float*)d_in[3];
    const float* W2  = (const float*)d_in[4];
    const float* b2  = (const float*)d_in[5];
    const float* W3  = (const float*)d_in[6];
    const float* b3  = (const float*)d_in[7];
    const float* fcW = (const float*)d_in[8];
    const float* fcb = (const float*)d_in[9];
    float* out = (float*)d_out;

    int FIN1 = in_sizes[2] / H;      // 10
    int N = in_sizes[0] / FIN1;      // 50000
    int E = in_sizes[1] / 2;         // 800000

    int gblocks = (N + 63) / 64;
    int ablocks = (N * 8 + 255) / 256;

    // Zero edge counters (Ctl is zeroed inside prep block 0, pre-barrier).
    void* cnt_ptr = nullptr;
    cudaGetSymbolAddress(&cnt_ptr, g_cnt);
    cudaMemsetAsync(cnt_ptr, 0, (size_t)N * sizeof(int));

    // Single-stream PDL chain; layer-3 GEMM folded into aggfinal (q @ W3).
    launch_pdl(prep_kernel, PREP_BLOCKS, 256, (const int*)ei, E, N);
    launch_pdl(gemm1_kernel, gblocks, 256, x, W1, N);
    launch_pdl(agg_kernel, ablocks, 256, N);
    launch_pdl(gemm2w_kernel, gblocks, 256, W2, b1, N);
    launch_pdl(aggfinal_kernel, ablocks, 256, N, b2, W3, b3, fcW, fcb, out);
}